// round 1
// baseline (speedup 1.0000x reference)
#include <cuda_runtime.h>
#include <math.h>

// Problem constants (fixed by the reference: B=64, P=1024, D=768)
#define Bsz   64
#define Pseq  1024
#define Ddim  768
#define SPLIT 2                       // CTAs per batch
#define ROWS_PER_CTA (Pseq / SPLIT)   // 512
#define NWARPS 16
#define NTHREADS (NWARPS * 32)        // 512
#define ROWS_PER_WARP (ROWS_PER_CTA / NWARPS)  // 32
#define DPL (Ddim / 32)               // 24 d-elements per lane

// Scratch (no cudaMalloc allowed) -------------------------------------------
__device__ float g_qw[Ddim];
__device__ float g_pm[Bsz * SPLIT];
__device__ float g_pl[Bsz * SPLIT];
__device__ float g_pacc[Bsz * SPLIT * Ddim];

// Kernel 1: qw[d] = (sum_e q[e] * W[e,d]) / sqrt(D) ---------------------------
__global__ void qw_kernel(const float* __restrict__ q, const float* __restrict__ W) {
    int d = blockIdx.x * blockDim.x + threadIdx.x;
    if (d >= Ddim) return;
    float acc = 0.f;
#pragma unroll 8
    for (int e = 0; e < Ddim; ++e)
        acc += q[e] * W[e * Ddim + d];
    g_qw[d] = acc * rsqrtf((float)Ddim);
}

// Kernel 2: per-(batch, split) online-softmax pooled partial ------------------
// One pass over z: each warp streams 32 rows, keeps the row in registers,
// maintains running (m, l, acc[768]) flash-style.
extern __shared__ float smem[];
__global__ __launch_bounds__(NTHREADS, 1)
void attn_partial_kernel(const float* __restrict__ z) {
    float* qw_s  = smem;                     // [Ddim]
    float* acc_s = smem + Ddim;              // [NWARPS * Ddim]
    float* m_s   = acc_s + NWARPS * Ddim;    // [NWARPS]
    float* l_s   = m_s + NWARPS;             // [NWARPS]

    const int bid  = blockIdx.x;
    const int b    = bid / SPLIT;
    const int s    = bid % SPLIT;
    const int tid  = threadIdx.x;
    const int w    = tid >> 5;
    const int lane = tid & 31;

    for (int t = tid; t < Ddim; t += NTHREADS) qw_s[t] = g_qw[t];
    __syncthreads();

    // Cache this lane's qw slice: d = i*128 + lane*4 + j  (i in 0..5, j in 0..3)
    float qw_r[DPL];
#pragma unroll
    for (int i = 0; i < 6; ++i) {
        float4 v = *reinterpret_cast<const float4*>(&qw_s[i * 128 + lane * 4]);
        qw_r[i * 4 + 0] = v.x; qw_r[i * 4 + 1] = v.y;
        qw_r[i * 4 + 2] = v.z; qw_r[i * 4 + 3] = v.w;
    }

    float m = -INFINITY, l = 0.f;
    float acc[DPL];
#pragma unroll
    for (int j = 0; j < DPL; ++j) acc[j] = 0.f;

    const float* zb = z + ((long)b * Pseq + (long)s * ROWS_PER_CTA
                           + (long)w * ROWS_PER_WARP) * Ddim;

    for (int r = 0; r < ROWS_PER_WARP; ++r) {
        const float* zr = zb + (long)r * Ddim;
        float zv[DPL];
#pragma unroll
        for (int i = 0; i < 6; ++i) {  // 6 coalesced LDG.128 per warp-row
            float4 v = *reinterpret_cast<const float4*>(&zr[i * 128 + lane * 4]);
            zv[i * 4 + 0] = v.x; zv[i * 4 + 1] = v.y;
            zv[i * 4 + 2] = v.z; zv[i * 4 + 3] = v.w;
        }
        float sc = 0.f;
#pragma unroll
        for (int j = 0; j < DPL; ++j) sc += zv[j] * qw_r[j];
#pragma unroll
        for (int o = 16; o; o >>= 1)
            sc += __shfl_xor_sync(0xffffffffu, sc, o);  // full butterfly: all lanes

        float m_new = fmaxf(m, sc);
        float alpha = __expf(m - m_new);   // exp(-inf)=0 on first row: safe
        float wp    = __expf(sc - m_new);
        l = l * alpha + wp;
#pragma unroll
        for (int j = 0; j < DPL; ++j) acc[j] = acc[j] * alpha + wp * zv[j];
        m = m_new;
    }

    // Stage per-warp state to smem
#pragma unroll
    for (int i = 0; i < 6; ++i) {
        float4 v = make_float4(acc[i * 4 + 0], acc[i * 4 + 1],
                               acc[i * 4 + 2], acc[i * 4 + 3]);
        *reinterpret_cast<float4*>(&acc_s[w * Ddim + i * 128 + lane * 4]) = v;
    }
    if (lane == 0) { m_s[w] = m; l_s[w] = l; }
    __syncthreads();

    // Cross-warp combine into one partial per CTA
    float M = -INFINITY;
#pragma unroll
    for (int ww = 0; ww < NWARPS; ++ww) M = fmaxf(M, m_s[ww]);

    for (int t = tid; t < Ddim; t += NTHREADS) {
        float sum = 0.f;
#pragma unroll
        for (int ww = 0; ww < NWARPS; ++ww)
            sum += __expf(m_s[ww] - M) * acc_s[ww * Ddim + t];
        g_pacc[bid * Ddim + t] = sum;
    }
    if (tid == 0) {
        float L = 0.f;
        for (int ww = 0; ww < NWARPS; ++ww)
            L += __expf(m_s[ww] - M) * l_s[ww];
        g_pm[bid] = M;
        g_pl[bid] = L;
    }
}

// Kernel 3: merge SPLIT partials per batch, normalize, write output -----------
__global__ void combine_kernel(float* __restrict__ out) {
    const int b = blockIdx.x;
    const int t = threadIdx.x;  // 0..Ddim-1

    float M = -INFINITY;
#pragma unroll
    for (int s = 0; s < SPLIT; ++s) M = fmaxf(M, g_pm[b * SPLIT + s]);

    float L = 0.f, num = 0.f;
#pragma unroll
    for (int s = 0; s < SPLIT; ++s) {
        float e = __expf(g_pm[b * SPLIT + s] - M);
        L   += e * g_pl[b * SPLIT + s];
        num += e * g_pacc[(b * SPLIT + s) * Ddim + t];
    }
    out[b * Ddim + t] = num / L;
}

// ----------------------------------------------------------------------------
extern "C" void kernel_launch(void* const* d_in, const int* in_sizes, int n_in,
                              void* d_out, int out_size) {
    // Identify inputs by element count (robust to ordering):
    //   z: 64*1024*768 = 50331648, q: 768, W: 768*768 = 589824
    const float* z = nullptr; const float* q = nullptr; const float* W = nullptr;
    for (int i = 0; i < n_in; ++i) {
        if (in_sizes[i] == Bsz * Pseq * Ddim)      z = (const float*)d_in[i];
        else if (in_sizes[i] == Ddim)              q = (const float*)d_in[i];
        else if (in_sizes[i] == Ddim * Ddim)       W = (const float*)d_in[i];
    }
    float* out = (float*)d_out;

    const int smem_bytes = (Ddim + NWARPS * Ddim + 2 * NWARPS) * (int)sizeof(float);
    cudaFuncSetAttribute(attn_partial_kernel,
                         cudaFuncAttributeMaxDynamicSharedMemorySize, smem_bytes);

    qw_kernel<<<(Ddim + 127) / 128, 128>>>(q, W);
    attn_partial_kernel<<<Bsz * SPLIT, NTHREADS, smem_bytes>>>(z);
    combine_kernel<<<Bsz, Ddim>>>(out);
}

// round 2
// speedup vs baseline: 2.1399x; 2.1399x over previous
#include <cuda_runtime.h>
#include <math.h>

// Problem constants (fixed by the reference: B=64, P=1024, D=768)
#define Bsz   64
#define Pseq  1024
#define Ddim  768
#define SPLIT 2                       // CTAs per batch
#define ROWS_PER_CTA (Pseq / SPLIT)   // 512
#define NWARPS 16
#define NTHREADS (NWARPS * 32)        // 512
#define ROWS_PER_WARP (ROWS_PER_CTA / NWARPS)  // 32
#define DPL (Ddim / 32)               // 24 d-elements per lane

#define ECHUNK 32                     // e-rows per qw-partial chunk
#define NCHUNK (Ddim / ECHUNK)        // 24 chunks

// Scratch (no cudaMalloc allowed) -------------------------------------------
__device__ float g_qw_part[NCHUNK][Ddim];
__device__ float g_pm[Bsz * SPLIT];
__device__ float g_pl[Bsz * SPLIT];
__device__ float g_pacc[Bsz * SPLIT * Ddim];

// Kernel 1: partial qw: g_qw_part[c][d] = sum_{e in chunk c} q[e] * W[e,d]
// Grid (NCHUNK, Ddim/128) = (24, 6) = 144 CTAs -> one full wave; each thread
// has a 32-long reduction instead of 768 -> latency chain cut 24x, and the
// whole 2.25 MB of W streams with full-chip MLP.
__global__ void qw_part_kernel(const float* __restrict__ q,
                               const float* __restrict__ W) {
    const int d  = blockIdx.y * 128 + threadIdx.x;
    const int e0 = blockIdx.x * ECHUNK;
    float acc = 0.f;
#pragma unroll
    for (int i = 0; i < ECHUNK; ++i)
        acc += q[e0 + i] * W[(long)(e0 + i) * Ddim + d];
    g_qw_part[blockIdx.x][d] = acc;
}

// Kernel 2: per-(batch, split) online-softmax pooled partial ------------------
// One pass over z: each warp streams 32 rows, keeps the row in registers,
// maintains running (m, l, acc[768]) flash-style. The qw chunk-reduction is
// folded into the smem staging (24x768 L2-hot reads per CTA, negligible).
extern __shared__ float smem[];
__global__ __launch_bounds__(NTHREADS, 1)
void attn_partial_kernel(const float* __restrict__ z) {
    float* qw_s  = smem;                     // [Ddim]
    float* acc_s = smem + Ddim;              // [NWARPS * Ddim]
    float* m_s   = acc_s + NWARPS * Ddim;    // [NWARPS]
    float* l_s   = m_s + NWARPS;             // [NWARPS]

    const int bid  = blockIdx.x;
    const int b    = bid / SPLIT;
    const int s    = bid % SPLIT;
    const int tid  = threadIdx.x;
    const int w    = tid >> 5;
    const int lane = tid & 31;

    const float scale = rsqrtf((float)Ddim);
    for (int t = tid; t < Ddim; t += NTHREADS) {
        float sum = 0.f;
#pragma unroll
        for (int c = 0; c < NCHUNK; ++c) sum += g_qw_part[c][t];
        qw_s[t] = sum * scale;
    }
    __syncthreads();

    // Cache this lane's qw slice: d = i*128 + lane*4 + j  (i in 0..5, j in 0..3)
    float qw_r[DPL];
#pragma unroll
    for (int i = 0; i < 6; ++i) {
        float4 v = *reinterpret_cast<const float4*>(&qw_s[i * 128 + lane * 4]);
        qw_r[i * 4 + 0] = v.x; qw_r[i * 4 + 1] = v.y;
        qw_r[i * 4 + 2] = v.z; qw_r[i * 4 + 3] = v.w;
    }

    float m = -INFINITY, l = 0.f;
    float acc[DPL];
#pragma unroll
    for (int j = 0; j < DPL; ++j) acc[j] = 0.f;

    const float* zb = z + ((long)b * Pseq + (long)s * ROWS_PER_CTA
                           + (long)w * ROWS_PER_WARP) * Ddim;

    for (int r = 0; r < ROWS_PER_WARP; ++r) {
        const float* zr = zb + (long)r * Ddim;
        float zv[DPL];
#pragma unroll
        for (int i = 0; i < 6; ++i) {  // 6 coalesced LDG.128 per warp-row
            float4 v = *reinterpret_cast<const float4*>(&zr[i * 128 + lane * 4]);
            zv[i * 4 + 0] = v.x; zv[i * 4 + 1] = v.y;
            zv[i * 4 + 2] = v.z; zv[i * 4 + 3] = v.w;
        }
        float sc = 0.f;
#pragma unroll
        for (int j = 0; j < DPL; ++j) sc += zv[j] * qw_r[j];
#pragma unroll
        for (int o = 16; o; o >>= 1)
            sc += __shfl_xor_sync(0xffffffffu, sc, o);  // full butterfly: all lanes

        float m_new = fmaxf(m, sc);
        float alpha = __expf(m - m_new);   // exp(-inf)=0 on first row: safe
        float wp    = __expf(sc - m_new);
        l = l * alpha + wp;
#pragma unroll
        for (int j = 0; j < DPL; ++j) acc[j] = acc[j] * alpha + wp * zv[j];
        m = m_new;
    }

    // Stage per-warp state to smem
#pragma unroll
    for (int i = 0; i < 6; ++i) {
        float4 v = make_float4(acc[i * 4 + 0], acc[i * 4 + 1],
                               acc[i * 4 + 2], acc[i * 4 + 3]);
        *reinterpret_cast<float4*>(&acc_s[w * Ddim + i * 128 + lane * 4]) = v;
    }
    if (lane == 0) { m_s[w] = m; l_s[w] = l; }
    __syncthreads();

    // Cross-warp combine into one partial per CTA
    float M = -INFINITY;
#pragma unroll
    for (int ww = 0; ww < NWARPS; ++ww) M = fmaxf(M, m_s[ww]);

    for (int t = tid; t < Ddim; t += NTHREADS) {
        float sum = 0.f;
#pragma unroll
        for (int ww = 0; ww < NWARPS; ++ww)
            sum += __expf(m_s[ww] - M) * acc_s[ww * Ddim + t];
        g_pacc[bid * Ddim + t] = sum;
    }
    if (tid == 0) {
        float L = 0.f;
        for (int ww = 0; ww < NWARPS; ++ww)
            L += __expf(m_s[ww] - M) * l_s[ww];
        g_pm[bid] = M;
        g_pl[bid] = L;
    }
}

// Kernel 3: merge SPLIT partials per batch, normalize, write output -----------
__global__ void combine_kernel(float* __restrict__ out) {
    const int b = blockIdx.x;
    const int t = threadIdx.x;  // 0..Ddim-1

    float M = -INFINITY;
#pragma unroll
    for (int s = 0; s < SPLIT; ++s) M = fmaxf(M, g_pm[b * SPLIT + s]);

    float L = 0.f, num = 0.f;
#pragma unroll
    for (int s = 0; s < SPLIT; ++s) {
        float e = __expf(g_pm[b * SPLIT + s] - M);
        L   += e * g_pl[b * SPLIT + s];
        num += e * g_pacc[(b * SPLIT + s) * Ddim + t];
    }
    out[b * Ddim + t] = num / L;
}

// ----------------------------------------------------------------------------
extern "C" void kernel_launch(void* const* d_in, const int* in_sizes, int n_in,
                              void* d_out, int out_size) {
    // Identify inputs by element count (robust to ordering):
    //   z: 64*1024*768 = 50331648, q: 768, W: 768*768 = 589824
    const float* z = nullptr; const float* q = nullptr; const float* W = nullptr;
    for (int i = 0; i < n_in; ++i) {
        if (in_sizes[i] == Bsz * Pseq * Ddim)      z = (const float*)d_in[i];
        else if (in_sizes[i] == Ddim)              q = (const float*)d_in[i];
        else if (in_sizes[i] == Ddim * Ddim)       W = (const float*)d_in[i];
    }
    float* out = (float*)d_out;

    const int smem_bytes = (Ddim + NWARPS * Ddim + 2 * NWARPS) * (int)sizeof(float);
    cudaFuncSetAttribute(attn_partial_kernel,
                         cudaFuncAttributeMaxDynamicSharedMemorySize, smem_bytes);

    dim3 qw_grid(NCHUNK, Ddim / 128);
    qw_part_kernel<<<qw_grid, 128>>>(q, W);
    attn_partial_kernel<<<Bsz * SPLIT, NTHREADS, smem_bytes>>>(z);
    combine_kernel<<<Bsz, Ddim>>>(out);
}